// round 10
// baseline (speedup 1.0000x reference)
#include <cuda_runtime.h>
#include <cuda_bf16.h>
#include <cstdint>
#include <cstddef>

#define B_    256
#define DIN_  512
#define H_    1024
#define DOUT_ 512
#define T_    256

// ---------------------------------------------------------------------------
// Device scratch.
// hs: split bf16 (hi+lo) + int8 correction operands (h8 = round(hi*64),
// h8l = round(lo*16384)).  GRU W: bf16 hi/lo + int8 (b8 = round(hi*127/sB),
// bl8 = round(lo*32512/sB)), per-row scale sB.  Scale identity:
// 64*32512 == 16384*127 == 2080768, so both cross-products share one s32 acc.
// ---------------------------------------------------------------------------
__device__ __nv_bfloat16 g_hs_hi[(size_t)(T_ + 1) * B_ * H_];
__device__ __nv_bfloat16 g_hs_lo[(size_t)(T_ + 1) * B_ * H_];
__device__ int8_t g_h8 [(size_t)(T_ + 1) * B_ * H_];
__device__ int8_t g_h8l[(size_t)(T_ + 1) * B_ * H_];
__device__ __nv_bfloat16 g_Whi[6 * H_ * H_];
__device__ __nv_bfloat16 g_Wlo[6 * H_ * H_];
__device__ int8_t g_W8 [(size_t)6 * H_ * H_];
__device__ int8_t g_W8l[(size_t)6 * H_ * H_];
__device__ float  g_wsc[6 * H_];
__device__ __nv_bfloat16 g_xhi[B_ * DIN_],  g_xlo[B_ * DIN_];
__device__ __nv_bfloat16 g_w1hi[H_ * DIN_], g_w1lo[H_ * DIN_];
__device__ __nv_bfloat16 g_w2hi[H_ * H_],   g_w2lo[H_ * H_];
__device__ __nv_bfloat16 g_t1hi[B_ * H_],   g_t1lo[B_ * H_];
__device__ __nv_bfloat16 g_owhi[DOUT_ * H_], g_owlo[DOUT_ * H_];

// ---------------------------------------------------------------------------
// Split of the pure-bf16 tensors (x, w1, w2, out_w).
// ---------------------------------------------------------------------------
#define SPLIT_TOTAL 2228224
__global__ void split_all_kernel(const float* __restrict__ x,
                                 const float* __restrict__ w1,
                                 const float* __restrict__ w2,
                                 const float* __restrict__ ow) {
    int i = blockIdx.x * blockDim.x + threadIdx.x;
    if (i >= SPLIT_TOTAL) return;
    const float* src;
    __nv_bfloat16 *hi, *lo;
    int off;
    if (i < 131072)        { src = x;   hi = g_xhi;  lo = g_xlo;  off = i; }
    else if (i < 655360)   { src = w1;  hi = g_w1hi; lo = g_w1lo; off = i - 131072; }
    else if (i < 1703936)  { src = w2;  hi = g_w2hi; lo = g_w2lo; off = i - 655360; }
    else                   { src = ow;  hi = g_owhi; lo = g_owlo; off = i - 1703936; }
    float v = src[off];
    __nv_bfloat16 h = __float2bfloat16(v);
    hi[off] = h;
    lo[off] = __float2bfloat16(v - __bfloat162float(h));
}

__device__ __forceinline__ int8_t clamp8(int v) {
    return (int8_t)max(-127, min(127, v));
}

// ---------------------------------------------------------------------------
// GRU weight prep: one block per row (6144 rows = [w_ih(3H); w_hh(3H)]).
// ---------------------------------------------------------------------------
__global__ void wprep_kernel(const float* __restrict__ wih,
                             const float* __restrict__ whh) {
    int row = blockIdx.x;
    const float* src = (row < 3 * H_) ? wih + (size_t)row * H_
                                      : whh + (size_t)(row - 3 * H_) * H_;
    __shared__ float red[256];
    float m = 0.0f;
    for (int i = threadIdx.x; i < H_; i += 256) m = fmaxf(m, fabsf(src[i]));
    red[threadIdx.x] = m;
    __syncthreads();
    for (int s = 128; s > 0; s >>= 1) {
        if (threadIdx.x < s) red[threadIdx.x] = fmaxf(red[threadIdx.x], red[threadIdx.x + s]);
        __syncthreads();
    }
    float sB = fmaxf(red[0], 1e-30f);
    if (threadIdx.x == 0) g_wsc[row] = sB;
    float inv  = 127.0f / sB;
    float invl = 32512.0f / sB;
    for (int i = threadIdx.x; i < H_; i += 256) {
        float w = src[i];
        __nv_bfloat16 bh = __float2bfloat16(w);
        float bhf = __bfloat162float(bh);
        __nv_bfloat16 bl = __float2bfloat16(w - bhf);
        size_t idx = (size_t)row * H_ + i;
        g_Whi[idx] = bh;
        g_Wlo[idx] = bl;
        g_W8[idx]  = clamp8(__float2int_rn(bhf * inv));
        g_W8l[idx] = clamp8(__float2int_rn(__bfloat162float(bl) * invl));
    }
}

// ---------------------------------------------------------------------------
// PTX helpers
// ---------------------------------------------------------------------------
__device__ __forceinline__ void mma_bf16(float* c,
                                         uint32_t a0, uint32_t a1, uint32_t a2, uint32_t a3,
                                         uint32_t b0, uint32_t b1) {
    asm volatile(
        "mma.sync.aligned.m16n8k16.row.col.f32.bf16.bf16.f32 "
        "{%0,%1,%2,%3}, {%4,%5,%6,%7}, {%8,%9}, {%0,%1,%2,%3};\n"
        : "+f"(c[0]), "+f"(c[1]), "+f"(c[2]), "+f"(c[3])
        : "r"(a0), "r"(a1), "r"(a2), "r"(a3), "r"(b0), "r"(b1));
}
__device__ __forceinline__ void mma_s8(int* c,
                                       uint32_t a0, uint32_t a1, uint32_t a2, uint32_t a3,
                                       uint32_t b0, uint32_t b1) {
    asm volatile(
        "mma.sync.aligned.m16n8k32.row.col.s32.s8.s8.s32 "
        "{%0,%1,%2,%3}, {%4,%5,%6,%7}, {%8,%9}, {%0,%1,%2,%3};\n"
        : "+r"(c[0]), "+r"(c[1]), "+r"(c[2]), "+r"(c[3])
        : "r"(a0), "r"(a1), "r"(a2), "r"(a3), "r"(b0), "r"(b1));
}
__device__ __forceinline__ void ldsm4(uint32_t& r0, uint32_t& r1,
                                      uint32_t& r2, uint32_t& r3, uint32_t addr) {
    asm volatile("ldmatrix.sync.aligned.m8n8.x4.shared.b16 {%0,%1,%2,%3}, [%4];\n"
                 : "=r"(r0), "=r"(r1), "=r"(r2), "=r"(r3) : "r"(addr));
}
__device__ __forceinline__ void cp16(uint32_t dst, const void* src) {
    asm volatile("cp.async.cg.shared.global [%0], [%1], 16;\n" :: "r"(dst), "l"(src));
}
__device__ __forceinline__ void cp_commit() {
    asm volatile("cp.async.commit_group;\n");
}
template <int N>
__device__ __forceinline__ void cp_wait() {
    asm volatile("cp.async.wait_group %0;\n" :: "n"(N));
}
__device__ __forceinline__ float sigm(float x) { return 1.0f / (1.0f + __expf(-x)); }
__device__ __forceinline__ float tanh_fast(float x) {
    float a = fabsf(x);
    float e = __expf(-2.0f * a);
    return copysignf((1.0f - e) / (1.0f + e), x);
}
// write one h element to all four representations
__device__ __forceinline__ void h_write(float v, size_t idx,
                                        __nv_bfloat16* dh, __nv_bfloat16* dl,
                                        int8_t* d8, int8_t* d8l) {
    __nv_bfloat16 hh = __float2bfloat16(v);
    float hf = __bfloat162float(hh);
    __nv_bfloat16 lo = __float2bfloat16(v - hf);
    dh[idx] = hh;
    dl[idx] = lo;
    d8[idx]  = clamp8(__float2int_rn(hf * 64.0f));
    d8l[idx] = clamp8(__float2int_rn(__bfloat162float(lo) * 16384.0f));
}

// ---------------------------------------------------------------------------
// Split-bf16 GEMM (proven). mode 1 also writes the int8 h limbs of slab 0.
// ---------------------------------------------------------------------------
__global__ __launch_bounds__(256, 2) void gemm3_kernel(
    int which, const float* __restrict__ bias, float* __restrict__ outf,
    int M, int N, int K, int mode)
{
    const __nv_bfloat16 *Ahi, *Alo, *Bhi, *Blo;
    if (which == 0)      { Ahi = g_xhi;  Alo = g_xlo;  Bhi = g_w1hi; Blo = g_w1lo; }
    else if (which == 1) { Ahi = g_t1hi; Alo = g_t1lo; Bhi = g_w2hi; Blo = g_w2lo; }
    else                 { Ahi = g_hs_hi + (size_t)B_ * H_; Alo = g_hs_lo + (size_t)B_ * H_;
                           Bhi = g_owhi; Blo = g_owlo; }
    const uint32_t* A32h = (const uint32_t*)Ahi;
    const uint32_t* A32l = (const uint32_t*)Alo;
    const uint32_t* B32h = (const uint32_t*)Bhi;
    const uint32_t* B32l = (const uint32_t*)Blo;

    __shared__ uint32_t sAh[128 * 20], sAl[128 * 20];
    __shared__ uint32_t sBh[64 * 20],  sBl[64 * 20];

    int tid  = threadIdx.x;
    int lane = tid & 31, warp = tid >> 5;
    int g = lane >> 2, t4 = lane & 3;
    int wm = warp >> 1, wn = warp & 1;
    int m0 = blockIdx.y * 128;
    int n0 = blockIdx.x * 64;
    int K2 = K >> 1;

    float acc[2][4][4];
#pragma unroll
    for (int a = 0; a < 2; a++)
#pragma unroll
        for (int b = 0; b < 4; b++)
#pragma unroll
            for (int c = 0; c < 4; c++) acc[a][b][c] = 0.0f;

    for (int k0 = 0; k0 < K; k0 += 32) {
        __syncthreads();
        int kc = k0 >> 1;
#pragma unroll
        for (int i = 0; i < 8; i++) {
            int e = tid + i * 256;
            int r = e >> 4, c = e & 15;
            size_t gi = (size_t)(m0 + r) * K2 + kc + c;
            sAh[r * 20 + c] = A32h[gi];
            sAl[r * 20 + c] = A32l[gi];
        }
#pragma unroll
        for (int i = 0; i < 4; i++) {
            int e = tid + i * 256;
            int r = e >> 4, c = e & 15;
            size_t gi = (size_t)(n0 + r) * K2 + kc + c;
            sBh[r * 20 + c] = B32h[gi];
            sBl[r * 20 + c] = B32l[gi];
        }
        __syncthreads();

#pragma unroll
        for (int kk = 0; kk < 2; kk++) {
            int base = kk * 8 + t4;
            uint32_t ah[2][4], al[2][4], bh[4][2], bl[4][2];
#pragma unroll
            for (int mf = 0; mf < 2; mf++) {
                int rb = wm * 32 + mf * 16;
                ah[mf][0] = sAh[(rb + g) * 20 + base];
                ah[mf][1] = sAh[(rb + g + 8) * 20 + base];
                ah[mf][2] = sAh[(rb + g) * 20 + base + 4];
                ah[mf][3] = sAh[(rb + g + 8) * 20 + base + 4];
                al[mf][0] = sAl[(rb + g) * 20 + base];
                al[mf][1] = sAl[(rb + g + 8) * 20 + base];
                al[mf][2] = sAl[(rb + g) * 20 + base + 4];
                al[mf][3] = sAl[(rb + g + 8) * 20 + base + 4];
            }
#pragma unroll
            for (int nf = 0; nf < 4; nf++) {
                int nb = wn * 32 + nf * 8 + g;
                bh[nf][0] = sBh[nb * 20 + base];
                bh[nf][1] = sBh[nb * 20 + base + 4];
                bl[nf][0] = sBl[nb * 20 + base];
                bl[nf][1] = sBl[nb * 20 + base + 4];
            }
#pragma unroll
            for (int mf = 0; mf < 2; mf++)
#pragma unroll
                for (int nf = 0; nf < 4; nf++)
                    mma_bf16(acc[mf][nf], ah[mf][0], ah[mf][1], ah[mf][2], ah[mf][3],
                             bh[nf][0], bh[nf][1]);
#pragma unroll
            for (int mf = 0; mf < 2; mf++)
#pragma unroll
                for (int nf = 0; nf < 4; nf++)
                    mma_bf16(acc[mf][nf], ah[mf][0], ah[mf][1], ah[mf][2], ah[mf][3],
                             bl[nf][0], bl[nf][1]);
#pragma unroll
            for (int mf = 0; mf < 2; mf++)
#pragma unroll
                for (int nf = 0; nf < 4; nf++)
                    mma_bf16(acc[mf][nf], al[mf][0], al[mf][1], al[mf][2], al[mf][3],
                             bh[nf][0], bh[nf][1]);
        }
    }

#pragma unroll
    for (int mf = 0; mf < 2; mf++)
#pragma unroll
        for (int nf = 0; nf < 4; nf++)
#pragma unroll
            for (int rr = 0; rr < 2; rr++)
#pragma unroll
                for (int cc = 0; cc < 2; cc++) {
                    int row = m0 + wm * 32 + mf * 16 + g + rr * 8;
                    int col = n0 + wn * 32 + nf * 8 + 2 * t4 + cc;
                    float v = acc[mf][nf][rr * 2 + cc] + bias[col];
                    if (mode == 0) {
                        __nv_bfloat16 h = __float2bfloat16(v);
                        g_t1hi[(size_t)row * N + col] = h;
                        g_t1lo[(size_t)row * N + col] =
                            __float2bfloat16(v - __bfloat162float(h));
                    } else if (mode == 1) {
                        outf[(size_t)row * N + col] = v;
                        h_write(v, (size_t)row * N + col,
                                g_hs_hi, g_hs_lo, g_h8, g_h8l);
                    } else {
                        int t = row >> 8;
                        int b = row & 255;
                        int Trt = M >> 8;
                        outf[(size_t)b * Trt * N + (size_t)t * N + col] = v;
                    }
                }
}

// ---------------------------------------------------------------------------
// Fused GRU step — hybrid HMMA main + IMMA corrections, 3-stage cp.async.
// BM=64, BN=16, grid (64, 4) = 256 CTAs, 2 CTAs/SM, 8 warps
// (warp_m = warp&3 : 16 rows; warp_g = warp>>2 : i-gates / h-gates).
// Stage layout (bytes): ah[0,5120) bh[5120,12800) a8[12800,15872)
// al8[15872,18944) b8[18944,23552) bl8[23552,28160).  bf16 rows 64B pad 80;
// int8 rows 32B pad 48 (conflict-free LDSM).  1280 x 16B chunks = 5/thread.
// ---------------------------------------------------------------------------
#define R_STG   28160
#define R_SMEM  (3 * R_STG)                // 84480 bytes

__global__ __launch_bounds__(256, 2) void gru_kernel(
    int t, const float* __restrict__ b_ih, const float* __restrict__ b_hh)
{
    extern __shared__ uint32_t smem[];

    int tid  = threadIdx.x;
    int lane = tid & 31, warp = tid >> 5;
    int g = lane >> 2, t4 = lane & 3;
    int warp_m = warp & 3, warp_g = warp >> 2;
    int m0 = blockIdx.y * 64;
    int j0 = blockIdx.x * 16;
    uint32_t sb = (uint32_t)__cvta_generic_to_shared(smem);

    // ---- per-thread load plan: 5 x 16B chunks per k32 tile ----
    const char* srcp[5];
    uint32_t    soff[5];
    uint32_t    kstp[5];                   // bytes advanced per tile
#pragma unroll
    for (int i = 0; i < 5; i++) {
        int c = tid + i * 256;             // 0..1279
        if (c < 256) {                     // ah: 64 rows x 4 chunks
            int row = c >> 2, ch = c & 3;
            srcp[i] = (const char*)(g_hs_hi + (size_t)t * B_ * H_
                                    + (size_t)(m0 + row) * H_) + ch * 16;
            soff[i] = row * 80 + ch * 16;
            kstp[i] = 64;
        } else if (c < 640) {              // bh: 96 rows x 4 chunks
            int rem = c - 256;
            int row = rem >> 2, ch = rem & 3;
            int gate = row >> 4, rj = row & 15;
            srcp[i] = (const char*)(g_Whi + (size_t)(gate * H_ + j0 + rj) * H_) + ch * 16;
            soff[i] = 5120 + row * 80 + ch * 16;
            kstp[i] = 64;
        } else if (c < 768) {              // a8: 64 rows x 2 chunks
            int rem = c - 640;
            int row = rem >> 1, ch = rem & 1;
            srcp[i] = (const char*)(g_h8 + (size_t)t * B_ * H_
                                    + (size_t)(m0 + row) * H_) + ch * 16;
            soff[i] = 12800 + row * 48 + ch * 16;
            kstp[i] = 32;
        } else if (c < 896) {              // al8
            int rem = c - 768;
            int row = rem >> 1, ch = rem & 1;
            srcp[i] = (const char*)(g_h8l + (size_t)t * B_ * H_
                                    + (size_t)(m0 + row) * H_) + ch * 16;
            soff[i] = 15872 + row * 48 + ch * 16;
            kstp[i] = 32;
        } else if (c < 1088) {             // b8: 96 rows x 2 chunks
            int rem = c - 896;
            int row = rem >> 1, ch = rem & 1;
            int gate = row >> 4, rj = row & 15;
            srcp[i] = (const char*)(g_W8 + (size_t)(gate * H_ + j0 + rj) * H_) + ch * 16;
            soff[i] = 18944 + row * 48 + ch * 16;
            kstp[i] = 32;
        } else {                           // bl8
            int rem = c - 1088;
            int row = rem >> 1, ch = rem & 1;
            int gate = row >> 4, rj = row & 15;
            srcp[i] = (const char*)(g_W8l + (size_t)(gate * H_ + j0 + rj) * H_) + ch * 16;
            soff[i] = 23552 + row * 48 + ch * 16;
            kstp[i] = 32;
        }
    }

    // LDSM address bases (byte offsets within a stage)
    int rb = warp_m * 16;
    uint32_t a_base  = (uint32_t)((rb + (lane & 15)) * 80 + (lane >> 4) * 16);
    int q = lane >> 3;
    uint32_t b_base  = (uint32_t)(5120 + (lane & 7) * 80 + (q >> 1) * 32 + (q & 1) * 16);
    uint32_t a8_base = (uint32_t)(12800 + (rb + (lane & 15)) * 48 + (lane >> 4) * 16);
    uint32_t b8_row  = (uint32_t)((lane >> 4) * 8 + (lane & 7));
    uint32_t b8_base = (uint32_t)(18944 + b8_row * 48 + ((lane >> 3) & 1) * 16);

    float af[3][2][4];
    int   ai[3][2][4];
#pragma unroll
    for (int a = 0; a < 3; a++)
#pragma unroll
        for (int b = 0; b < 2; b++)
#pragma unroll
            for (int c = 0; c < 4; c++) { af[a][b][c] = 0.0f; ai[a][b][c] = 0; }

    auto load_tile = [&](int kt) {
        if (kt < 32) {
            uint32_t sbase = sb + (uint32_t)(kt % 3) * R_STG;
#pragma unroll
            for (int i = 0; i < 5; i++)
                cp16(sbase + soff[i], srcp[i] + (size_t)kt * kstp[i]);
        }
        cp_commit();
    };

    load_tile(0);
    load_tile(1);

    for (int kt = 0; kt < 32; kt++) {
        cp_wait<1>();
        __syncthreads();
        load_tile(kt + 2);

        uint32_t bufB = sb + (uint32_t)(kt % 3) * R_STG;

        uint32_t ah[2][4];
#pragma unroll
        for (int kk = 0; kk < 2; kk++)
            ldsm4(ah[kk][0], ah[kk][1], ah[kk][2], ah[kk][3],
                  bufB + a_base + kk * 32);
        uint32_t a8f[4], l8f[4];
        ldsm4(a8f[0], a8f[1], a8f[2], a8f[3], bufB + a8_base);
        ldsm4(l8f[0], l8f[1], l8f[2], l8f[3], bufB + a8_base + 3072);

#pragma unroll
        for (int gi = 0; gi < 3; gi++) {
            int gate = warp_g * 3 + gi;
            uint32_t bh0[4], bh1[4], b8f[4], bl8f[4];
            uint32_t bb = bufB + b_base + (uint32_t)gate * 1280;
            ldsm4(bh0[0], bh0[1], bh0[2], bh0[3], bb);
            ldsm4(bh1[0], bh1[1], bh1[2], bh1[3], bb + 640);
            uint32_t b8a = bufB + b8_base + (uint32_t)gate * 768;
            ldsm4(b8f[0],  b8f[1],  b8f[2],  b8f[3],  b8a);
            ldsm4(bl8f[0], bl8f[1], bl8f[2], bl8f[3], b8a + 4608);
            // interleave 4 independent acc chains
            mma_bf16(af[gi][0], ah[0][0], ah[0][1], ah[0][2], ah[0][3], bh0[0], bh0[1]);
            mma_bf16(af[gi][1], ah[0][0], ah[0][1], ah[0][2], ah[0][3], bh1[0], bh1[1]);
            mma_s8 (ai[gi][0], a8f[0], a8f[1], a8f[2], a8f[3], bl8f[0], bl8f[1]);
            mma_s8 (ai[gi][1], a8f[0], a8f[1], a8f[2], a8f[3], bl8f[2], bl8f[3]);
            mma_bf16(af[gi][0], ah[1][0], ah[1][1], ah[1][2], ah[1][3], bh0[2], bh0[3]);
            mma_bf16(af[gi][1], ah[1][0], ah[1][1], ah[1][2], ah[1][3], bh1[2], bh1[3]);
            mma_s8 (ai[gi][0], l8f[0], l8f[1], l8f[2], l8f[3], b8f[0], b8f[1]);
            mma_s8 (ai[gi][1], l8f[0], l8f[1], l8f[2], l8f[3], b8f[2], b8f[3]);
        }
    }

    cp_wait<0>();
    __syncthreads();

    // ---- fold int corrections into float gates: g = af + sB*ai/2080768 ----
    const float cI = 4.8059288e-7f;        // 1/2080768
    float gv[3][2][4];
#pragma unroll
    for (int gi = 0; gi < 3; gi++)
#pragma unroll
        for (int nf = 0; nf < 2; nf++)
#pragma unroll
            for (int ci = 0; ci < 4; ci++) {
                int j = j0 + nf * 8 + 2 * t4 + (ci & 1);
                float s = g_wsc[(warp_g * 3 + gi) * H_ + j];
                gv[gi][nf][ci] = af[gi][nf][ci] + s * cI * (float)ai[gi][nf][ci];
            }

    // ---- gate exchange: h-gate warps -> smem -> i-gate warps ----
    float* xch = (float*)smem;             // 12 KB, stages dead
    if (warp_g == 1) {
        int base = (warp_m * 32 + lane) * 24;
#pragma unroll
        for (int a = 0; a < 3; a++)
#pragma unroll
            for (int b = 0; b < 2; b++)
#pragma unroll
                for (int c = 0; c < 4; c++)
                    xch[base + a * 8 + b * 4 + c] = gv[a][b][c];
    }
    __syncthreads();

    if (warp_g == 0) {
        int base = (warp_m * 32 + lane) * 24;
        const __nv_bfloat16* src_hi = g_hs_hi + (size_t)t * B_ * H_;
        const __nv_bfloat16* src_lo = g_hs_lo + (size_t)t * B_ * H_;
        size_t dsl = (size_t)(t + 1) * B_ * H_;

#pragma unroll
        for (int nf = 0; nf < 2; nf++)
#pragma unroll
            for (int cc = 0; cc < 2; cc++) {
                int j = j0 + nf * 8 + 2 * t4 + cc;
                float bir = b_ih[j], biz = b_ih[H_ + j], bin = b_ih[2 * H_ + j];
                float bhr = b_hh[j], bhz = b_hh[H_ + j], bhn = b_hh[2 * H_ + j];
#pragma unroll
                for (int rr = 0; rr < 2; rr++) {
                    int m  = m0 + warp_m * 16 + g + rr * 8;
                    int ci = rr * 2 + cc;
                    float ir  = gv[0][nf][ci] + bir;
                    float iz  = gv[1][nf][ci] + biz;
                    float inn = gv[2][nf][ci] + bin;
                    float hr  = xch[base + 0 * 8 + nf * 4 + ci] + bhr;
                    float hz  = xch[base + 1 * 8 + nf * 4 + ci] + bhz;
                    float hn  = xch[base + 2 * 8 + nf * 4 + ci] + bhn;
                    float r  = sigm(ir + hr);
                    float z  = sigm(iz + hz);
                    float nn = tanh_fast(inn + r * hn);
                    size_t idx = (size_t)m * H_ + j;
                    float hold = __bfloat162float(src_hi[idx]) + __bfloat162float(src_lo[idx]);
                    float hnew = (1.0f - z) * nn + z * hold;
                    h_write(hnew, dsl + idx, g_hs_hi, g_hs_lo, g_h8, g_h8l);
                }
            }
    }
}

// ---------------------------------------------------------------------------
// Host launcher: graph-capturable.
// ---------------------------------------------------------------------------
extern "C" void kernel_launch(void* const* d_in, const int* in_sizes, int n_in,
                              void* d_out, int out_size) {
    const float* x     = (const float*)d_in[0];
    const float* w1    = (const float*)d_in[1];
    const float* b1    = (const float*)d_in[2];
    const float* w2    = (const float*)d_in[3];
    const float* b2    = (const float*)d_in[4];
    const float* w_ih  = (const float*)d_in[5];
    const float* b_ih  = (const float*)d_in[6];
    const float* w_hh  = (const float*)d_in[7];
    const float* b_hh  = (const float*)d_in[8];
    const float* out_w = (const float*)d_in[9];
    const float* out_b = (const float*)d_in[10];
    float* out = (float*)d_out;

    int T = (out_size - B_ * H_) / (B_ * DOUT_);   // = 256
    if (T > T_) T = T_;

    static bool attr_done = false;
    if (!attr_done) {
        cudaFuncSetAttribute(gru_kernel,
                             cudaFuncAttributeMaxDynamicSharedMemorySize, R_SMEM);
        attr_done = true;
    }

    split_all_kernel<<<(SPLIT_TOTAL + 255) / 256, 256>>>(x, w1, w2, out_w);
    wprep_kernel<<<6 * H_, 256>>>(w_ih, w_hh);

    // FCN layer 1: t1 = x @ w1^T + b1
    gemm3_kernel<<<dim3(H_ / 64, B_ / 128), 256>>>(0, b1, nullptr, B_, H_, DIN_, 0);
    // FCN layer 2: latent -> d_out latent slice + hs slab 0 (all 4 reps)
    gemm3_kernel<<<dim3(H_ / 64, B_ / 128), 256>>>(
        1, b2, out + (size_t)B_ * T * DOUT_, B_, H_, H_, 1);

    // GRU recurrence (hybrid HMMA + IMMA)
    for (int t = 0; t < T; t++)
        gru_kernel<<<dim3(H_ / 16, B_ / 64), 256, R_SMEM>>>(t, b_ih, b_hh);

    // Output projection (permuted write)
    gemm3_kernel<<<dim3(DOUT_ / 64, (T * B_) / 128), 256>>>(
        2, out_b, out, T * B_, DOUT_, H_, 2);
}

// round 12
// speedup vs baseline: 1.5556x; 1.5556x over previous
#include <cuda_runtime.h>
#include <cuda_bf16.h>
#include <cstdint>
#include <cstddef>

#define B_    256
#define DIN_  512
#define H_    1024
#define DOUT_ 512
#define T_    256

// ---------------------------------------------------------------------------
// Device scratch.
// hs: split bf16 (hi+lo) + int8 correction operands (h8 = round(hi*64),
// h8l = round(lo*16384)).  GRU W: bf16 hi/lo + int8 (b8 = round(hi*127/sB),
// bl8 = round(lo*32512/sB)), per-row scale sB.  Scale identity:
// 64*32512 == 16384*127 == 2080768, so both cross-products share one s32 acc.
// ---------------------------------------------------------------------------
__device__ __nv_bfloat16 g_hs_hi[(size_t)(T_ + 1) * B_ * H_];
__device__ __nv_bfloat16 g_hs_lo[(size_t)(T_ + 1) * B_ * H_];
__device__ int8_t g_h8 [(size_t)(T_ + 1) * B_ * H_];
__device__ int8_t g_h8l[(size_t)(T_ + 1) * B_ * H_];
__device__ __nv_bfloat16 g_Whi[6 * H_ * H_];
__device__ __nv_bfloat16 g_Wlo[6 * H_ * H_];
__device__ int8_t g_W8 [(size_t)6 * H_ * H_];
__device__ int8_t g_W8l[(size_t)6 * H_ * H_];
__device__ float  g_wsc[6 * H_];
__device__ __nv_bfloat16 g_xhi[B_ * DIN_],  g_xlo[B_ * DIN_];
__device__ __nv_bfloat16 g_w1hi[H_ * DIN_], g_w1lo[H_ * DIN_];
__device__ __nv_bfloat16 g_w2hi[H_ * H_],   g_w2lo[H_ * H_];
__device__ __nv_bfloat16 g_t1hi[B_ * H_],   g_t1lo[B_ * H_];
__device__ __nv_bfloat16 g_owhi[DOUT_ * H_], g_owlo[DOUT_ * H_];

// ---------------------------------------------------------------------------
// Split of the pure-bf16 tensors (x, w1, w2, out_w).
// ---------------------------------------------------------------------------
#define SPLIT_TOTAL 2228224
__global__ void split_all_kernel(const float* __restrict__ x,
                                 const float* __restrict__ w1,
                                 const float* __restrict__ w2,
                                 const float* __restrict__ ow) {
    int i = blockIdx.x * blockDim.x + threadIdx.x;
    if (i >= SPLIT_TOTAL) return;
    const float* src;
    __nv_bfloat16 *hi, *lo;
    int off;
    if (i < 131072)        { src = x;   hi = g_xhi;  lo = g_xlo;  off = i; }
    else if (i < 655360)   { src = w1;  hi = g_w1hi; lo = g_w1lo; off = i - 131072; }
    else if (i < 1703936)  { src = w2;  hi = g_w2hi; lo = g_w2lo; off = i - 655360; }
    else                   { src = ow;  hi = g_owhi; lo = g_owlo; off = i - 1703936; }
    float v = src[off];
    __nv_bfloat16 h = __float2bfloat16(v);
    hi[off] = h;
    lo[off] = __float2bfloat16(v - __bfloat162float(h));
}

__device__ __forceinline__ int8_t clamp8(int v) {
    return (int8_t)max(-127, min(127, v));
}

// ---------------------------------------------------------------------------
// GRU weight prep: one block per row (6144 rows = [w_ih; w_hh]).
// ---------------------------------------------------------------------------
__global__ void wprep_kernel(const float* __restrict__ wih,
                             const float* __restrict__ whh) {
    int row = blockIdx.x;
    const float* src = (row < 3 * H_) ? wih + (size_t)row * H_
                                      : whh + (size_t)(row - 3 * H_) * H_;
    __shared__ float red[256];
    float m = 0.0f;
    for (int i = threadIdx.x; i < H_; i += 256) m = fmaxf(m, fabsf(src[i]));
    red[threadIdx.x] = m;
    __syncthreads();
    for (int s = 128; s > 0; s >>= 1) {
        if (threadIdx.x < s) red[threadIdx.x] = fmaxf(red[threadIdx.x], red[threadIdx.x + s]);
        __syncthreads();
    }
    float sB = fmaxf(red[0], 1e-30f);
    if (threadIdx.x == 0) g_wsc[row] = sB;
    float inv  = 127.0f / sB;
    float invl = 32512.0f / sB;
    for (int i = threadIdx.x; i < H_; i += 256) {
        float w = src[i];
        __nv_bfloat16 bh = __float2bfloat16(w);
        float bhf = __bfloat162float(bh);
        __nv_bfloat16 bl = __float2bfloat16(w - bhf);
        size_t idx = (size_t)row * H_ + i;
        g_Whi[idx] = bh;
        g_Wlo[idx] = bl;
        g_W8[idx]  = clamp8(__float2int_rn(bhf * inv));
        g_W8l[idx] = clamp8(__float2int_rn(__bfloat162float(bl) * invl));
    }
}

// ---------------------------------------------------------------------------
// PTX helpers
// ---------------------------------------------------------------------------
__device__ __forceinline__ void mma_bf16(float* c,
                                         uint32_t a0, uint32_t a1, uint32_t a2, uint32_t a3,
                                         uint32_t b0, uint32_t b1) {
    asm volatile(
        "mma.sync.aligned.m16n8k16.row.col.f32.bf16.bf16.f32 "
        "{%0,%1,%2,%3}, {%4,%5,%6,%7}, {%8,%9}, {%0,%1,%2,%3};\n"
        : "+f"(c[0]), "+f"(c[1]), "+f"(c[2]), "+f"(c[3])
        : "r"(a0), "r"(a1), "r"(a2), "r"(a3), "r"(b0), "r"(b1));
}
__device__ __forceinline__ void mma_s8(int* c,
                                       uint32_t a0, uint32_t a1, uint32_t a2, uint32_t a3,
                                       uint32_t b0, uint32_t b1) {
    asm volatile(
        "mma.sync.aligned.m16n8k32.row.col.s32.s8.s8.s32 "
        "{%0,%1,%2,%3}, {%4,%5,%6,%7}, {%8,%9}, {%0,%1,%2,%3};\n"
        : "+r"(c[0]), "+r"(c[1]), "+r"(c[2]), "+r"(c[3])
        : "r"(a0), "r"(a1), "r"(a2), "r"(a3), "r"(b0), "r"(b1));
}
__device__ __forceinline__ void ldsm4(uint32_t& r0, uint32_t& r1,
                                      uint32_t& r2, uint32_t& r3, uint32_t addr) {
    asm volatile("ldmatrix.sync.aligned.m8n8.x4.shared.b16 {%0,%1,%2,%3}, [%4];\n"
                 : "=r"(r0), "=r"(r1), "=r"(r2), "=r"(r3) : "r"(addr));
}
__device__ __forceinline__ void cp16(uint32_t dst, const void* src) {
    asm volatile("cp.async.cg.shared.global [%0], [%1], 16;\n" :: "r"(dst), "l"(src));
}
__device__ __forceinline__ void cp_commit() {
    asm volatile("cp.async.commit_group;\n");
}
template <int N>
__device__ __forceinline__ void cp_wait() {
    asm volatile("cp.async.wait_group %0;\n" :: "n"(N));
}
__device__ __forceinline__ float sigm(float x) { return 1.0f / (1.0f + __expf(-x)); }
__device__ __forceinline__ float tanh_fast(float x) {
    float a = fabsf(x);
    float e = __expf(-2.0f * a);
    return copysignf((1.0f - e) / (1.0f + e), x);
}
__device__ __forceinline__ void h_write(float v, size_t idx,
                                        __nv_bfloat16* dh, __nv_bfloat16* dl,
                                        int8_t* d8, int8_t* d8l) {
    __nv_bfloat16 hh = __float2bfloat16(v);
    float hf = __bfloat162float(hh);
    __nv_bfloat16 lo = __float2bfloat16(v - hf);
    dh[idx] = hh;
    dl[idx] = lo;
    d8[idx]  = clamp8(__float2int_rn(hf * 64.0f));
    d8l[idx] = clamp8(__float2int_rn(__bfloat162float(lo) * 16384.0f));
}

// smem offset + per-tile global stride for load chunk c (pure function of c;
// recomputed inside the loop so ptxas can rematerialize instead of spill).
__device__ __forceinline__ void plan_chunk(int c, uint32_t& off, int& kst) {
    if (c < 256)       { off = (uint32_t)((c >> 2) * 80 + (c & 3) * 16);              kst = 64; }
    else if (c < 640)  { int r = c - 256;
                         off = (uint32_t)(5120 + (r >> 2) * 80 + (r & 3) * 16);       kst = 64; }
    else if (c < 768)  { int r = c - 640;
                         off = (uint32_t)(12800 + (r >> 1) * 48 + (r & 1) * 16);      kst = 32; }
    else if (c < 896)  { int r = c - 768;
                         off = (uint32_t)(15872 + (r >> 1) * 48 + (r & 1) * 16);      kst = 32; }
    else if (c < 1088) { int r = c - 896;
                         off = (uint32_t)(18944 + (r >> 1) * 48 + (r & 1) * 16);      kst = 32; }
    else               { int r = c - 1088;
                         off = (uint32_t)(23552 + (r >> 1) * 48 + (r & 1) * 16);      kst = 32; }
}

// ---------------------------------------------------------------------------
// Split-bf16 GEMM (proven). mode 1 also writes the int8 h limbs of slab 0.
// ---------------------------------------------------------------------------
__global__ __launch_bounds__(256, 2) void gemm3_kernel(
    int which, const float* __restrict__ bias, float* __restrict__ outf,
    int M, int N, int K, int mode)
{
    const __nv_bfloat16 *Ahi, *Alo, *Bhi, *Blo;
    if (which == 0)      { Ahi = g_xhi;  Alo = g_xlo;  Bhi = g_w1hi; Blo = g_w1lo; }
    else if (which == 1) { Ahi = g_t1hi; Alo = g_t1lo; Bhi = g_w2hi; Blo = g_w2lo; }
    else                 { Ahi = g_hs_hi + (size_t)B_ * H_; Alo = g_hs_lo + (size_t)B_ * H_;
                           Bhi = g_owhi; Blo = g_owlo; }
    const uint32_t* A32h = (const uint32_t*)Ahi;
    const uint32_t* A32l = (const uint32_t*)Alo;
    const uint32_t* B32h = (const uint32_t*)Bhi;
    const uint32_t* B32l = (const uint32_t*)Blo;

    __shared__ uint32_t sAh[128 * 20], sAl[128 * 20];
    __shared__ uint32_t sBh[64 * 20],  sBl[64 * 20];

    int tid  = threadIdx.x;
    int lane = tid & 31, warp = tid >> 5;
    int g = lane >> 2, t4 = lane & 3;
    int wm = warp >> 1, wn = warp & 1;
    int m0 = blockIdx.y * 128;
    int n0 = blockIdx.x * 64;
    int K2 = K >> 1;

    float acc[2][4][4];
#pragma unroll
    for (int a = 0; a < 2; a++)
#pragma unroll
        for (int b = 0; b < 4; b++)
#pragma unroll
            for (int c = 0; c < 4; c++) acc[a][b][c] = 0.0f;

    for (int k0 = 0; k0 < K; k0 += 32) {
        __syncthreads();
        int kc = k0 >> 1;
#pragma unroll
        for (int i = 0; i < 8; i++) {
            int e = tid + i * 256;
            int r = e >> 4, c = e & 15;
            size_t gi = (size_t)(m0 + r) * K2 + kc + c;
            sAh[r * 20 + c] = A32h[gi];
            sAl[r * 20 + c] = A32l[gi];
        }
#pragma unroll
        for (int i = 0; i < 4; i++) {
            int e = tid + i * 256;
            int r = e >> 4, c = e & 15;
            size_t gi = (size_t)(n0 + r) * K2 + kc + c;
            sBh[r * 20 + c] = B32h[gi];
            sBl[r * 20 + c] = B32l[gi];
        }
        __syncthreads();

#pragma unroll
        for (int kk = 0; kk < 2; kk++) {
            int base = kk * 8 + t4;
            uint32_t ah[2][4], al[2][4], bh[4][2], bl[4][2];
#pragma unroll
            for (int mf = 0; mf < 2; mf++) {
                int rb = wm * 32 + mf * 16;
                ah[mf][0] = sAh[(rb + g) * 20 + base];
                ah[mf][1] = sAh[(rb + g + 8) * 20 + base];
                ah[mf][2] = sAh[(rb + g) * 20 + base + 4];
                ah[mf][3] = sAh[(rb + g + 8) * 20 + base + 4];
                al[mf][0] = sAl[(rb + g) * 20 + base];
                al[mf][1] = sAl[(rb + g + 8) * 20 + base];
                al[mf][2] = sAl[(rb + g) * 20 + base + 4];
                al[mf][3] = sAl[(rb + g + 8) * 20 + base + 4];
            }
#pragma unroll
            for (int nf = 0; nf < 4; nf++) {
                int nb = wn * 32 + nf * 8 + g;
                bh[nf][0] = sBh[nb * 20 + base];
                bh[nf][1] = sBh[nb * 20 + base + 4];
                bl[nf][0] = sBl[nb * 20 + base];
                bl[nf][1] = sBl[nb * 20 + base + 4];
            }
#pragma unroll
            for (int mf = 0; mf < 2; mf++)
#pragma unroll
                for (int nf = 0; nf < 4; nf++)
                    mma_bf16(acc[mf][nf], ah[mf][0], ah[mf][1], ah[mf][2], ah[mf][3],
                             bh[nf][0], bh[nf][1]);
#pragma unroll
            for (int mf = 0; mf < 2; mf++)
#pragma unroll
                for (int nf = 0; nf < 4; nf++)
                    mma_bf16(acc[mf][nf], ah[mf][0], ah[mf][1], ah[mf][2], ah[mf][3],
                             bl[nf][0], bl[nf][1]);
#pragma unroll
            for (int mf = 0; mf < 2; mf++)
#pragma unroll
                for (int nf = 0; nf < 4; nf++)
                    mma_bf16(acc[mf][nf], al[mf][0], al[mf][1], al[mf][2], al[mf][3],
                             bh[nf][0], bh[nf][1]);
        }
    }

#pragma unroll
    for (int mf = 0; mf < 2; mf++)
#pragma unroll
        for (int nf = 0; nf < 4; nf++)
#pragma unroll
            for (int rr = 0; rr < 2; rr++)
#pragma unroll
                for (int cc = 0; cc < 2; cc++) {
                    int row = m0 + wm * 32 + mf * 16 + g + rr * 8;
                    int col = n0 + wn * 32 + nf * 8 + 2 * t4 + cc;
                    float v = acc[mf][nf][rr * 2 + cc] + bias[col];
                    if (mode == 0) {
                        __nv_bfloat16 h = __float2bfloat16(v);
                        g_t1hi[(size_t)row * N + col] = h;
                        g_t1lo[(size_t)row * N + col] =
                            __float2bfloat16(v - __bfloat162float(h));
                    } else if (mode == 1) {
                        outf[(size_t)row * N + col] = v;
                        h_write(v, (size_t)row * N + col,
                                g_hs_hi, g_hs_lo, g_h8, g_h8l);
                    } else {
                        int t = row >> 8;
                        int b = row & 255;
                        int Trt = M >> 8;
                        outf[(size_t)b * Trt * N + (size_t)t * N + col] = v;
                    }
                }
}

// ---------------------------------------------------------------------------
// Fused GRU step — hybrid HMMA main + IMMA corrections, 3-stage cp.async.
// Math identical to r10 (rel_err 2.94e-4 validated).  Addressing identical to
// r10 (64-bit per-chunk pointers — the r11 cross-array 32-bit anchor offsets
// caused the illegal access and are gone).  Register diet: smem offsets +
// strides rematerialized via plan_chunk; corrections folded in place into af.
// Stage layout (bytes): ah[0,5120) bh[5120,12800) a8[12800,15872)
// al8[15872,18944) b8[18944,23552) bl8[23552,28160).
// ---------------------------------------------------------------------------
#define R_STG   28160
#define R_SMEM  (3 * R_STG)                // 84480 bytes

__global__ __launch_bounds__(256, 2) void gru_kernel(
    int t, const float* __restrict__ b_ih, const float* __restrict__ b_hh)
{
    extern __shared__ uint32_t smem[];

    int tid  = threadIdx.x;
    int lane = tid & 31, warp = tid >> 5;
    int g = lane >> 2, t4 = lane & 3;
    int warp_m = warp & 3, warp_g = warp >> 2;
    int m0 = blockIdx.y * 64;
    int j0 = blockIdx.x * 16;
    uint32_t sb = (uint32_t)__cvta_generic_to_shared(smem);

    // ---- per-thread load plan: 5 x 64-bit source pointers (r10-proven) ----
    const char* srcp[5];
#pragma unroll
    for (int i = 0; i < 5; i++) {
        int c = tid + i * 256;             // 0..1279
        if (c < 256) {                     // ah: 64 rows x 4 chunks
            int row = c >> 2, ch = c & 3;
            srcp[i] = (const char*)(g_hs_hi + (size_t)t * B_ * H_
                                    + (size_t)(m0 + row) * H_) + ch * 16;
        } else if (c < 640) {              // bh: 96 rows x 4 chunks
            int rem = c - 256;
            int row = rem >> 2, ch = rem & 3;
            int gate = row >> 4, rj = row & 15;
            srcp[i] = (const char*)(g_Whi + (size_t)(gate * H_ + j0 + rj) * H_) + ch * 16;
        } else if (c < 768) {              // a8: 64 rows x 2 chunks
            int rem = c - 640;
            int row = rem >> 1, ch = rem & 1;
            srcp[i] = (const char*)(g_h8 + (size_t)t * B_ * H_
                                    + (size_t)(m0 + row) * H_) + ch * 16;
        } else if (c < 896) {              // al8
            int rem = c - 768;
            int row = rem >> 1, ch = rem & 1;
            srcp[i] = (const char*)(g_h8l + (size_t)t * B_ * H_
                                    + (size_t)(m0 + row) * H_) + ch * 16;
        } else if (c < 1088) {             // b8: 96 rows x 2 chunks
            int rem = c - 896;
            int row = rem >> 1, ch = rem & 1;
            int gate = row >> 4, rj = row & 15;
            srcp[i] = (const char*)(g_W8 + (size_t)(gate * H_ + j0 + rj) * H_) + ch * 16;
        } else {                           // bl8
            int rem = c - 1088;
            int row = rem >> 1, ch = rem & 1;
            int gate = row >> 4, rj = row & 15;
            srcp[i] = (const char*)(g_W8l + (size_t)(gate * H_ + j0 + rj) * H_) + ch * 16;
        }
    }

    // LDSM address bases (byte offsets within a stage)
    int rb = warp_m * 16;
    uint32_t a_base  = (uint32_t)((rb + (lane & 15)) * 80 + (lane >> 4) * 16);
    int q = lane >> 3;
    uint32_t b_base  = (uint32_t)(5120 + (lane & 7) * 80 + (q >> 1) * 32 + (q & 1) * 16);
    uint32_t a8_base = (uint32_t)(12800 + (rb + (lane & 15)) * 48 + (lane >> 4) * 16);
    uint32_t b8_row  = (uint32_t)((lane >> 4) * 8 + (lane & 7));
    uint32_t b8_base = (uint32_t)(18944 + b8_row * 48 + ((lane >> 3) & 1) * 16);

    float af[3][2][4];
    int   ai[3][2][4];
#pragma unroll
    for (int a = 0; a < 3; a++)
#pragma unroll
        for (int b = 0; b < 2; b++)
#pragma unroll
            for (int c = 0; c < 4; c++) { af[a][b][c] = 0.0f; ai[a][b][c] = 0; }

    auto load_tile = [&](int kt) {
        if (kt < 32) {
            uint32_t sbase = sb + (uint32_t)(kt % 3) * R_STG;
#pragma unroll
            for (int i = 0; i < 5; i++) {
                uint32_t off; int kst;
                plan_chunk(tid + i * 256, off, kst);
                cp16(sbase + off, srcp[i] + (size_t)kt * kst);
            }
        }
        cp_commit();
    };

    load_tile(0);
    load_tile(1);

    for (int kt = 0; kt < 32; kt++) {
        cp_wait<1>();
        __syncthreads();
        load_tile(kt + 2);

        uint32_t bufB = sb + (uint32_t)(kt % 3) * R_STG;

        uint32_t ah[2][4];
#pragma unroll
        for (int kk = 0; kk < 2; kk++)
            ldsm4(ah[kk][0], ah[kk][1], ah[kk][2], ah[kk][3],
                  bufB + a_base + kk * 32);
        uint32_t a8f[4], l8f[4];
        ldsm4(a8f[0], a8f[1], a8f[2], a8f[3], bufB + a8_base);
        ldsm4(l8f[0], l8f[1], l8f[2], l8f[3], bufB + a8_base + 3072);

#pragma unroll
        for (int gi = 0; gi < 3; gi++) {
            int gate = warp_g * 3 + gi;
            uint32_t bh0[4], bh1[4], b8f[4], bl8f[4];
            uint32_t bb = bufB + b_base + (uint32_t)gate * 1280;
            ldsm4(bh0[0], bh0[1], bh0[2], bh0[3], bb);
            ldsm4(bh1[0], bh1[1], bh1[2], bh1[3], bb + 640);
            uint32_t b8a = bufB + b8_base + (uint32_t)gate * 768;
            ldsm4(b8f[0],  b8f[1],  b8f[2],  b8f[3],  b8a);
            ldsm4(bl8f[0], bl8f[1], bl8f[2], bl8f[3], b8a + 4608);
            // interleave 4 independent acc chains
            mma_bf16(af[gi][0], ah[0][0], ah[0][1], ah[0][2], ah[0][3], bh0[0], bh0[1]);
            mma_bf16(af[gi][1], ah[0][0], ah[0][1], ah[0][2], ah[0][3], bh1[0], bh1[1]);
            mma_s8 (ai[gi][0], a8f[0], a8f[1], a8f[2], a8f[3], bl8f[0], bl8f[1]);
            mma_s8 (ai[gi][1], a8f[0], a8f[1], a8f[2], a8f[3], bl8f[2], bl8f[3]);
            mma_bf16(af[gi][0], ah[1][0], ah[1][1], ah[1][2], ah[1][3], bh0[2], bh0[3]);
            mma_bf16(af[gi][1], ah[1][0], ah[1][1], ah[1][2], ah[1][3], bh1[2], bh1[3]);
            mma_s8 (ai[gi][0], l8f[0], l8f[1], l8f[2], l8f[3], b8f[0], b8f[1]);
            mma_s8 (ai[gi][1], l8f[0], l8f[1], l8f[2], l8f[3], b8f[2], b8f[3]);
        }
    }

    cp_wait<0>();
    __syncthreads();

    // ---- fold int corrections in place: af += sB * ai / 2080768 ----
    const float cI = 4.8059288e-7f;        // 1/2080768
#pragma unroll
    for (int gi = 0; gi < 3; gi++)
#pragma unroll
        for (int nf = 0; nf < 2; nf++)
#pragma unroll
            for (int ci = 0; ci < 4; ci++) {
                int j = j0 + nf * 8 + 2 * t4 + (ci & 1);
                float s = g_wsc[(warp_g * 3 + gi) * H_ + j];
                af[gi][nf][ci] += s * cI * (float)ai[gi][nf][ci];
            }

    // ---- gate exchange: h-gate warps -> smem -> i-gate warps ----
    float* xch = (float*)smem;             // 12 KB, stages dead
    if (warp_g == 1) {
        int base = (warp_m * 32 + lane) * 24;
#pragma unroll
        for (int a = 0; a < 3; a++)
#pragma unroll
            for (int b = 0; b < 2; b++)
#pragma unroll
                for (int c = 0; c < 4; c++)
                    xch[base + a * 8 + b * 4 + c] = af[a][b][c];
    }
    __syncthreads();

    if (warp_g == 0) {
        int base = (warp_m * 32 + lane) * 24;
        const __nv_bfloat16* src_hi = g_hs_hi + (size_t)t * B_ * H_;
        const __nv_bfloat16* src_lo = g_hs_lo + (size_t)t * B_ * H_;
        size_t dsl = (size_t)(t + 1) * B_ * H_;

#pragma unroll
        for (int nf = 0; nf < 2; nf++)
#pragma unroll
            for (int cc = 0; cc < 2; cc++) {
                int j = j0 + nf * 8 + 2 * t4 + cc;
                float bir = b_ih[j], biz = b_ih[H_ + j], bin = b_ih[2 * H_ + j];
                float bhr = b_hh[j], bhz = b_hh[H_ + j], bhn = b_hh[2 * H_ + j];
#pragma unroll
                for (int rr = 0; rr < 2; rr++) {
                    int m  = m0 + warp_m * 16 + g + rr * 8;
                    int ci = rr * 2 + cc;
                    float ir  = af[0][nf][ci] + bir;
                    float iz  = af[1][nf][ci] + biz;
                    float inn = af[2][nf][ci] + bin;
                    float hr  = xch[base + 0 * 8 + nf * 4 + ci] + bhr;
                    float hz  = xch[base + 1 * 8 + nf * 4 + ci] + bhz;
                    float hn  = xch[base + 2 * 8 + nf * 4 + ci] + bhn;
                    float r  = sigm(ir + hr);
                    float z  = sigm(iz + hz);
                    float nn = tanh_fast(inn + r * hn);
                    size_t idx = (size_t)m * H_ + j;
                    float hold = __bfloat162float(src_hi[idx]) + __bfloat162float(src_lo[idx]);
                    float hnew = (1.0f - z) * nn + z * hold;
                    h_write(hnew, dsl + idx, g_hs_hi, g_hs_lo, g_h8, g_h8l);
                }
            }
    }
}

// ---------------------------------------------------------------------------
// Host launcher: graph-capturable.
// ---------------------------------------------------------------------------
extern "C" void kernel_launch(void* const* d_in, const int* in_sizes, int n_in,
                              void* d_out, int out_size) {
    const float* x     = (const float*)d_in[0];
    const float* w1    = (const float*)d_in[1];
    const float* b1    = (const float*)d_in[2];
    const float* w2    = (const float*)d_in[3];
    const float* b2    = (const float*)d_in[4];
    const float* w_ih  = (const float*)d_in[5];
    const float* b_ih  = (const float*)d_in[6];
    const float* w_hh  = (const float*)d_in[7];
    const float* b_hh  = (const float*)d_in[8];
    const float* out_w = (const float*)d_in[9];
    const float* out_b = (const float*)d_in[10];
    float* out = (float*)d_out;

    int T = (out_size - B_ * H_) / (B_ * DOUT_);   // = 256
    if (T > T_) T = T_;

    static bool attr_done = false;
    if (!attr_done) {
        cudaFuncSetAttribute(gru_kernel,
                             cudaFuncAttributeMaxDynamicSharedMemorySize, R_SMEM);
        attr_done = true;
    }

    split_all_kernel<<<(SPLIT_TOTAL + 255) / 256, 256>>>(x, w1, w2, out_w);
    wprep_kernel<<<6 * H_, 256>>>(w_ih, w_hh);

    // FCN layer 1: t1 = x @ w1^T + b1
    gemm3_kernel<<<dim3(H_ / 64, B_ / 128), 256>>>(0, b1, nullptr, B_, H_, DIN_, 0);
    // FCN layer 2: latent -> d_out latent slice + hs slab 0 (all 4 reps)
    gemm3_kernel<<<dim3(H_ / 64, B_ / 128), 256>>>(
        1, b2, out + (size_t)B_ * T * DOUT_, B_, H_, H_, 1);

    // GRU recurrence (hybrid HMMA + IMMA, register-dieted, safe addressing)
    for (int t = 0; t < T; t++)
        gru_kernel<<<dim3(H_ / 16, B_ / 64), 256, R_SMEM>>>(t, b_ih, b_hh);

    // Output projection (permuted write)
    gemm3_kernel<<<dim3(DOUT_ / 64, (T * B_) / 128), 256>>>(
        2, out_b, out, T * B_, DOUT_, H_, 2);
}

// round 14
// speedup vs baseline: 3.9320x; 2.5276x over previous
#include <cuda_runtime.h>
#include <cuda_bf16.h>
#include <cstdint>
#include <cstddef>

// Problem constants (shapes fixed by the dataset).
#define B_    256
#define DIN_  512
#define H_    1024
#define DOUT_ 512
#define T_    256

// ---------------------------------------------------------------------------
// Device scratch. hs: T+1 slabs of [B, H] split bf16 (hi+lo).
// GRU weights use the gate-merged form (4 blocks of H rows):
//   block 0: W_ir + W_hr   (r-gate combined)
//   block 1: W_iz + W_hz   (z-gate combined)
//   block 2: W_in          (i_n)
//   block 3: W_hn          (h_n)
// r/z only ever use i+h sums (same input h), so 4 GEMM blocks suffice: -33% MMAs.
// ---------------------------------------------------------------------------
__device__ __nv_bfloat16 g_hs_hi[(size_t)(T_ + 1) * B_ * H_];
__device__ __nv_bfloat16 g_hs_lo[(size_t)(T_ + 1) * B_ * H_];
__device__ __nv_bfloat16 g_W4hi[(size_t)4 * H_ * H_];
__device__ __nv_bfloat16 g_W4lo[(size_t)4 * H_ * H_];
__device__ __nv_bfloat16 g_xhi[B_ * DIN_],  g_xlo[B_ * DIN_];
__device__ __nv_bfloat16 g_w1hi[H_ * DIN_], g_w1lo[H_ * DIN_];
__device__ __nv_bfloat16 g_w2hi[H_ * H_],   g_w2lo[H_ * H_];
__device__ __nv_bfloat16 g_t1hi[B_ * H_],   g_t1lo[B_ * H_];
__device__ __nv_bfloat16 g_owhi[DOUT_ * H_], g_owlo[DOUT_ * H_];

// ---------------------------------------------------------------------------
// Split of x, w1, w2, out_w into bf16 hi/lo.
// ---------------------------------------------------------------------------
#define SPLIT_TOTAL 2228224
__global__ void split_all_kernel(const float* __restrict__ x,
                                 const float* __restrict__ w1,
                                 const float* __restrict__ w2,
                                 const float* __restrict__ ow) {
    int i = blockIdx.x * blockDim.x + threadIdx.x;
    if (i >= SPLIT_TOTAL) return;
    const float* src;
    __nv_bfloat16 *hi, *lo;
    int off;
    if (i < 131072)        { src = x;   hi = g_xhi;  lo = g_xlo;  off = i; }
    else if (i < 655360)   { src = w1;  hi = g_w1hi; lo = g_w1lo; off = i - 131072; }
    else if (i < 1703936)  { src = w2;  hi = g_w2hi; lo = g_w2lo; off = i - 655360; }
    else                   { src = ow;  hi = g_owhi; lo = g_owlo; off = i - 1703936; }
    float v = src[off];
    __nv_bfloat16 h = __float2bfloat16(v);
    hi[off] = h;
    lo[off] = __float2bfloat16(v - __bfloat162float(h));
}

// ---------------------------------------------------------------------------
// Gate-merged GRU weight prep: 4H rows. Sums computed in fp32, then the
// identical exact hi/lo bf16 split as everything else.
// ---------------------------------------------------------------------------
__global__ void wprep4_kernel(const float* __restrict__ wih,
                              const float* __restrict__ whh) {
    int row = blockIdx.x;                  // 0 .. 4H-1
    int gate = row >> 10;                  // /H_
    int j    = row & (H_ - 1);
    for (int i = threadIdx.x; i < H_; i += 256) {
        float v;
        if (gate == 0)      v = wih[(size_t)j * H_ + i]            + whh[(size_t)j * H_ + i];
        else if (gate == 1) v = wih[(size_t)(H_ + j) * H_ + i]     + whh[(size_t)(H_ + j) * H_ + i];
        else if (gate == 2) v = wih[(size_t)(2 * H_ + j) * H_ + i];
        else                v = whh[(size_t)(2 * H_ + j) * H_ + i];
        __nv_bfloat16 h = __float2bfloat16(v);
        size_t idx = (size_t)row * H_ + i;
        g_W4hi[idx] = h;
        g_W4lo[idx] = __float2bfloat16(v - __bfloat162float(h));
    }
}

// ---------------------------------------------------------------------------
// PTX helpers
// ---------------------------------------------------------------------------
__device__ __forceinline__ void mma_bf16(float* c,
                                         uint32_t a0, uint32_t a1, uint32_t a2, uint32_t a3,
                                         uint32_t b0, uint32_t b1) {
    asm volatile(
        "mma.sync.aligned.m16n8k16.row.col.f32.bf16.bf16.f32 "
        "{%0,%1,%2,%3}, {%4,%5,%6,%7}, {%8,%9}, {%0,%1,%2,%3};\n"
        : "+f"(c[0]), "+f"(c[1]), "+f"(c[2]), "+f"(c[3])
        : "r"(a0), "r"(a1), "r"(a2), "r"(a3), "r"(b0), "r"(b1));
}
__device__ __forceinline__ void ldsm4(uint32_t& r0, uint32_t& r1,
                                      uint32_t& r2, uint32_t& r3, uint32_t addr) {
    asm volatile("ldmatrix.sync.aligned.m8n8.x4.shared.b16 {%0,%1,%2,%3}, [%4];\n"
                 : "=r"(r0), "=r"(r1), "=r"(r2), "=r"(r3) : "r"(addr));
}
__device__ __forceinline__ void cp16(uint32_t dst, const void* src) {
    asm volatile("cp.async.cg.shared.global [%0], [%1], 16;\n" :: "r"(dst), "l"(src));
}
__device__ __forceinline__ void cp_commit() {
    asm volatile("cp.async.commit_group;\n");
}
template <int N>
__device__ __forceinline__ void cp_wait() {
    asm volatile("cp.async.wait_group %0;\n" :: "n"(N));
}
__device__ __forceinline__ float sigm(float x) { return 1.0f / (1.0f + __expf(-x)); }
__device__ __forceinline__ float tanh_fast(float x) {
    float a = fabsf(x);
    float e = __expf(-2.0f * a);
    return copysignf((1.0f - e) / (1.0f + e), x);
}

// ---------------------------------------------------------------------------
// Split-bf16 GEMM (proven r9 version). BM=128, BN=64, BK=32; 256 threads.
// ---------------------------------------------------------------------------
__global__ __launch_bounds__(256, 2) void gemm3_kernel(
    int which, const float* __restrict__ bias, float* __restrict__ outf,
    int M, int N, int K, int mode)
{
    const __nv_bfloat16 *Ahi, *Alo, *Bhi, *Blo;
    if (which == 0)      { Ahi = g_xhi;  Alo = g_xlo;  Bhi = g_w1hi; Blo = g_w1lo; }
    else if (which == 1) { Ahi = g_t1hi; Alo = g_t1lo; Bhi = g_w2hi; Blo = g_w2lo; }
    else                 { Ahi = g_hs_hi + (size_t)B_ * H_; Alo = g_hs_lo + (size_t)B_ * H_;
                           Bhi = g_owhi; Blo = g_owlo; }
    const uint32_t* A32h = (const uint32_t*)Ahi;
    const uint32_t* A32l = (const uint32_t*)Alo;
    const uint32_t* B32h = (const uint32_t*)Bhi;
    const uint32_t* B32l = (const uint32_t*)Blo;

    __shared__ uint32_t sAh[128 * 20], sAl[128 * 20];
    __shared__ uint32_t sBh[64 * 20],  sBl[64 * 20];

    int tid  = threadIdx.x;
    int lane = tid & 31, warp = tid >> 5;
    int g = lane >> 2, t4 = lane & 3;
    int wm = warp >> 1, wn = warp & 1;
    int m0 = blockIdx.y * 128;
    int n0 = blockIdx.x * 64;
    int K2 = K >> 1;

    float acc[2][4][4];
#pragma unroll
    for (int a = 0; a < 2; a++)
#pragma unroll
        for (int b = 0; b < 4; b++)
#pragma unroll
            for (int c = 0; c < 4; c++) acc[a][b][c] = 0.0f;

    for (int k0 = 0; k0 < K; k0 += 32) {
        __syncthreads();
        int kc = k0 >> 1;
#pragma unroll
        for (int i = 0; i < 8; i++) {
            int e = tid + i * 256;
            int r = e >> 4, c = e & 15;
            size_t gi = (size_t)(m0 + r) * K2 + kc + c;
            sAh[r * 20 + c] = A32h[gi];
            sAl[r * 20 + c] = A32l[gi];
        }
#pragma unroll
        for (int i = 0; i < 4; i++) {
            int e = tid + i * 256;
            int r = e >> 4, c = e & 15;
            size_t gi = (size_t)(n0 + r) * K2 + kc + c;
            sBh[r * 20 + c] = B32h[gi];
            sBl[r * 20 + c] = B32l[gi];
        }
        __syncthreads();

#pragma unroll
        for (int kk = 0; kk < 2; kk++) {
            int base = kk * 8 + t4;
            uint32_t ah[2][4], al[2][4], bh[4][2], bl[4][2];
#pragma unroll
            for (int mf = 0; mf < 2; mf++) {
                int rb = wm * 32 + mf * 16;
                ah[mf][0] = sAh[(rb + g) * 20 + base];
                ah[mf][1] = sAh[(rb + g + 8) * 20 + base];
                ah[mf][2] = sAh[(rb + g) * 20 + base + 4];
                ah[mf][3] = sAh[(rb + g + 8) * 20 + base + 4];
                al[mf][0] = sAl[(rb + g) * 20 + base];
                al[mf][1] = sAl[(rb + g + 8) * 20 + base];
                al[mf][2] = sAl[(rb + g) * 20 + base + 4];
                al[mf][3] = sAl[(rb + g + 8) * 20 + base + 4];
            }
#pragma unroll
            for (int nf = 0; nf < 4; nf++) {
                int nb = wn * 32 + nf * 8 + g;
                bh[nf][0] = sBh[nb * 20 + base];
                bh[nf][1] = sBh[nb * 20 + base + 4];
                bl[nf][0] = sBl[nb * 20 + base];
                bl[nf][1] = sBl[nb * 20 + base + 4];
            }
#pragma unroll
            for (int mf = 0; mf < 2; mf++)
#pragma unroll
                for (int nf = 0; nf < 4; nf++)
                    mma_bf16(acc[mf][nf], ah[mf][0], ah[mf][1], ah[mf][2], ah[mf][3],
                             bh[nf][0], bh[nf][1]);
#pragma unroll
            for (int mf = 0; mf < 2; mf++)
#pragma unroll
                for (int nf = 0; nf < 4; nf++)
                    mma_bf16(acc[mf][nf], ah[mf][0], ah[mf][1], ah[mf][2], ah[mf][3],
                             bl[nf][0], bl[nf][1]);
#pragma unroll
            for (int mf = 0; mf < 2; mf++)
#pragma unroll
                for (int nf = 0; nf < 4; nf++)
                    mma_bf16(acc[mf][nf], al[mf][0], al[mf][1], al[mf][2], al[mf][3],
                             bh[nf][0], bh[nf][1]);
        }
    }

#pragma unroll
    for (int mf = 0; mf < 2; mf++)
#pragma unroll
        for (int nf = 0; nf < 4; nf++)
#pragma unroll
            for (int rr = 0; rr < 2; rr++)
#pragma unroll
                for (int cc = 0; cc < 2; cc++) {
                    int row = m0 + wm * 32 + mf * 16 + g + rr * 8;
                    int col = n0 + wn * 32 + nf * 8 + 2 * t4 + cc;
                    float v = acc[mf][nf][rr * 2 + cc] + bias[col];
                    if (mode == 0) {
                        __nv_bfloat16 h = __float2bfloat16(v);
                        g_t1hi[(size_t)row * N + col] = h;
                        g_t1lo[(size_t)row * N + col] =
                            __float2bfloat16(v - __bfloat162float(h));
                    } else if (mode == 1) {
                        outf[(size_t)row * N + col] = v;
                        __nv_bfloat16 h = __float2bfloat16(v);
                        g_hs_hi[(size_t)row * N + col] = h;
                        g_hs_lo[(size_t)row * N + col] =
                            __float2bfloat16(v - __bfloat162float(h));
                    } else {
                        int t = row >> 8;               // row = t*B + b
                        int b = row & 255;
                        int Trt = M >> 8;
                        outf[(size_t)b * Trt * N + (size_t)t * N + col] = v;
                    }
                }
}

// ---------------------------------------------------------------------------
// Fused GRU step — gate-merged (4 blocks), r9 structure + 4-stage cp.async.
// BM=64, BN=16, grid (64 j, 4 m) = 256 CTAs, 2 CTAs/SM.
// 8 warps: warp_m = warp&3 (16 rows), warp_g = warp>>2:
//   group 0 -> gates {r_comb, z_comb}, group 1 -> gates {i_n, h_n}.
// Stage (u32, stride 20): Ah[64*20] Al[64*20] Bh[64*20] Bl[64*20] = 5120 u32.
// Per tile: wait_group 2 -> ONE sync -> issue stage kt+3 -> compute stage kt.
// ---------------------------------------------------------------------------
#define STAGES  4
#define R_BUF   (256 * 20)                 // u32 per stage (5120)
#define R_SMEM  (STAGES * R_BUF * 4)       // 81920 bytes dynamic

__global__ __launch_bounds__(256, 2) void gru_kernel(
    int t, const float* __restrict__ b_ih, const float* __restrict__ b_hh)
{
    extern __shared__ uint32_t smem[];

    int tid  = threadIdx.x;
    int lane = tid & 31, warp = tid >> 5;
    int g = lane >> 2, t4 = lane & 3;
    int warp_m = warp & 3, warp_g = warp >> 2;
    int m0 = blockIdx.y * 64;
    int j0 = blockIdx.x * 16;
    uint32_t sb = (uint32_t)__cvta_generic_to_shared(smem);

    // ---- per-thread load plan: 4 x 16B chunks per k32 tile ----
    const uint4* srcp[4];
    uint32_t     soff[4];                  // byte offset within a stage
#pragma unroll
    for (int i = 0; i < 4; i++) {
        int c = tid + i * 256;             // 0..1023
        if (c < 512) {                     // A (h): hi then lo, 64 rows x 4 chunks
            int half = c >> 8, rem = c & 255;
            int row = rem >> 2, ch = rem & 3;
            const __nv_bfloat16* base =
                (half ? g_hs_lo : g_hs_hi) + (size_t)t * B_ * H_;
            srcp[i] = (const uint4*)base + (size_t)(m0 + row) * 128 + ch;
            soff[i] = (uint32_t)(half * 1280 + row * 20 + ch * 4) * 4;
        } else {                           // W4: hi then lo, 64 rows x 4 chunks
            int c2 = c - 512;              // 0..511
            int half = c2 >> 8, rem = c2 & 255;
            int row = rem >> 2, ch = rem & 3;
            int gate = row >> 4, rj = row & 15;
            const __nv_bfloat16* base = half ? g_W4lo : g_W4hi;
            srcp[i] = (const uint4*)base + (size_t)(gate * H_ + j0 + rj) * 128 + ch;
            soff[i] = (uint32_t)(2560 + half * 1280 + row * 20 + ch * 4) * 4;
        }
    }

    // LDSM address bases (byte offsets within a stage)
    int rb = warp_m * 16;
    uint32_t a_base = (uint32_t)((rb + (lane & 15)) * 80 + (lane >> 4) * 16);
    int q = lane >> 3;
    uint32_t b_base = (uint32_t)(10240 + (lane & 7) * 80 + (q >> 1) * 32 + (q & 1) * 16);

    float acc[2][2][4];
#pragma unroll
    for (int a = 0; a < 2; a++)
#pragma unroll
        for (int b = 0; b < 2; b++)
#pragma unroll
            for (int c = 0; c < 4; c++) acc[a][b][c] = 0.0f;

    // ---- async loader: tile kt -> stage kt & 3 ----
    auto load_tile = [&](int kt) {
        if (kt < 32) {
            uint32_t sbase = sb + (uint32_t)(kt & (STAGES - 1)) * (R_BUF * 4);
#pragma unroll
            for (int i = 0; i < 4; i++)
                cp16(sbase + soff[i], srcp[i] + kt * 4);
        }
        cp_commit();
    };

    // Prologue: stages 0..2 in flight
    load_tile(0);
    load_tile(1);
    load_tile(2);

    for (int kt = 0; kt < 32; kt++) {
        cp_wait<2>();                      // tile kt resident
        __syncthreads();                   // all warps done reading stage (kt-1)&3
        load_tile(kt + 3);                 // refill the stage freed by kt-1

        uint32_t bufB = sb + (uint32_t)(kt & (STAGES - 1)) * (R_BUF * 4);

        // A fragments via LDSM.x4 (hi and lo, both k16 chunks); Al at +5120B
        uint32_t ah[2][4], al[2][4];
#pragma unroll
        for (int kk = 0; kk < 2; kk++) {
            uint32_t aaddr = bufB + a_base + kk * 32;
            ldsm4(ah[kk][0], ah[kk][1], ah[kk][2], ah[kk][3], aaddr);
            ldsm4(al[kk][0], al[kk][1], al[kk][2], al[kk][3], aaddr + 5120);
        }

        // 2 gates for this warp's gate-group; interleave the 2 nf chains.
#pragma unroll
        for (int gi = 0; gi < 2; gi++) {
            int gate = warp_g * 2 + gi;
            uint32_t baddr = bufB + b_base + (uint32_t)((gate * 16) * 80);
            uint32_t bh0[4], bl0[4], bh1[4], bl1[4];
            ldsm4(bh0[0], bh0[1], bh0[2], bh0[3], baddr);
            ldsm4(bl0[0], bl0[1], bl0[2], bl0[3], baddr + 5120);
            ldsm4(bh1[0], bh1[1], bh1[2], bh1[3], baddr + 640);
            ldsm4(bl1[0], bl1[1], bl1[2], bl1[3], baddr + 640 + 5120);
            mma_bf16(acc[gi][0], ah[0][0], ah[0][1], ah[0][2], ah[0][3], bh0[0], bh0[1]);
            mma_bf16(acc[gi][1], ah[0][0], ah[0][1], ah[0][2], ah[0][3], bh1[0], bh1[1]);
            mma_bf16(acc[gi][0], ah[1][0], ah[1][1], ah[1][2], ah[1][3], bh0[2], bh0[3]);
            mma_bf16(acc[gi][1], ah[1][0], ah[1][1], ah[1][2], ah[1][3], bh1[2], bh1[3]);
            mma_bf16(acc[gi][0], ah[0][0], ah[0][1], ah[0][2], ah[0][3], bl0[0], bl0[1]);
            mma_bf16(acc[gi][1], ah[0][0], ah[0][1], ah[0][2], ah[0][3], bl1[0], bl1[1]);
            mma_bf16(acc[gi][0], ah[1][0], ah[1][1], ah[1][2], ah[1][3], bl0[2], bl0[3]);
            mma_bf16(acc[gi][1], ah[1][0], ah[1][1], ah[1][2], ah[1][3], bl1[2], bl1[3]);
            mma_bf16(acc[gi][0], al[0][0], al[0][1], al[0][2], al[0][3], bh0[0], bh0[1]);
            mma_bf16(acc[gi][1], al[0][0], al[0][1], al[0][2], al[0][3], bh1[0], bh1[1]);
            mma_bf16(acc[gi][0], al[1][0], al[1][1], al[1][2], al[1][3], bh0[2], bh0[3]);
            mma_bf16(acc[gi][1], al[1][0], al[1][1], al[1][2], al[1][3], bh1[2], bh1[3]);
        }
    }

    cp_wait<0>();
    __syncthreads();

    // ---- gate exchange: n-gate warps (group 1) -> smem -> r/z warps ----
    float* xch = (float*)smem;             // 4*32*16 floats = 8 KB (stages dead)
    if (warp_g == 1) {
        int base = (warp_m * 32 + lane) * 16;
#pragma unroll
        for (int a = 0; a < 2; a++)
#pragma unroll
            for (int b = 0; b < 2; b++)
#pragma unroll
                for (int c = 0; c < 4; c++)
                    xch[base + a * 8 + b * 4 + c] = acc[a][b][c];
    }
    __syncthreads();

    if (warp_g == 0) {
        int base = (warp_m * 32 + lane) * 16;
        const __nv_bfloat16* src_hi = g_hs_hi + (size_t)t * B_ * H_;
        const __nv_bfloat16* src_lo = g_hs_lo + (size_t)t * B_ * H_;
        __nv_bfloat16* dst_hi = g_hs_hi + (size_t)(t + 1) * B_ * H_;
        __nv_bfloat16* dst_lo = g_hs_lo + (size_t)(t + 1) * B_ * H_;

#pragma unroll
        for (int nf = 0; nf < 2; nf++)
#pragma unroll
            for (int cc = 0; cc < 2; cc++) {
                int j = j0 + nf * 8 + 2 * t4 + cc;
                float br = b_ih[j]          + b_hh[j];
                float bz = b_ih[H_ + j]     + b_hh[H_ + j];
                float bin = b_ih[2 * H_ + j];
                float bhn = b_hh[2 * H_ + j];
#pragma unroll
                for (int rr = 0; rr < 2; rr++) {
                    int m  = m0 + warp_m * 16 + g + rr * 8;
                    int ci = rr * 2 + cc;
                    float r  = sigm(acc[0][nf][ci] + br);
                    float z  = sigm(acc[1][nf][ci] + bz);
                    float inn = xch[base + 0 * 8 + nf * 4 + ci] + bin;   // i_n
                    float hn  = xch[base + 1 * 8 + nf * 4 + ci] + bhn;   // h_n
                    float nn = tanh_fast(inn + r * hn);
                    size_t idx = (size_t)m * H_ + j;
                    float hold = __bfloat162float(src_hi[idx]) + __bfloat162float(src_lo[idx]);
                    float hnew = (1.0f - z) * nn + z * hold;
                    __nv_bfloat16 hh = __float2bfloat16(hnew);
                    dst_hi[idx] = hh;
                    dst_lo[idx] = __float2bfloat16(hnew - __bfloat162float(hh));
                }
            }
    }
}

// ---------------------------------------------------------------------------
// Host launcher: graph-capturable.
// ---------------------------------------------------------------------------
extern "C" void kernel_launch(void* const* d_in, const int* in_sizes, int n_in,
                              void* d_out, int out_size) {
    const float* x     = (const float*)d_in[0];
    const float* w1    = (const float*)d_in[1];
    const float* b1    = (const float*)d_in[2];
    const float* w2    = (const float*)d_in[3];
    const float* b2    = (const float*)d_in[4];
    const float* w_ih  = (const float*)d_in[5];
    const float* b_ih  = (const float*)d_in[6];
    const float* w_hh  = (const float*)d_in[7];
    const float* b_hh  = (const float*)d_in[8];
    const float* out_w = (const float*)d_in[9];
    const float* out_b = (const float*)d_in[10];
    float* out = (float*)d_out;

    int T = (out_size - B_ * H_) / (B_ * DOUT_);   // = 256
    if (T > T_) T = T_;

    static bool attr_done = false;
    if (!attr_done) {
        cudaFuncSetAttribute(gru_kernel,
                             cudaFuncAttributeMaxDynamicSharedMemorySize, R_SMEM);
        attr_done = true;
    }

    split_all_kernel<<<(SPLIT_TOTAL + 255) / 256, 256>>>(x, w1, w2, out_w);
    wprep4_kernel<<<4 * H_, 256>>>(w_ih, w_hh);

    // FCN layer 1: t1 = x @ w1^T + b1
    gemm3_kernel<<<dim3(H_ / 64, B_ / 128), 256>>>(0, b1, nullptr, B_, H_, DIN_, 0);
    // FCN layer 2: latent -> d_out latent slice + hs slab 0
    gemm3_kernel<<<dim3(H_ / 64, B_ / 128), 256>>>(
        1, b2, out + (size_t)B_ * T * DOUT_, B_, H_, H_, 1);

    // GRU recurrence (gate-merged: 4 blocks, 33% fewer MMAs)
    for (int t = 0; t < T; t++)
        gru_kernel<<<dim3(H_ / 16, B_ / 64), 256, R_SMEM>>>(t, b_ih, b_hh);

    // Output projection (permuted write)
    gemm3_kernel<<<dim3(DOUT_ / 64, (T * B_) / 128), 256>>>(
        2, out_b, out, T * B_, DOUT_, H_, 2);
}